// round 1
// baseline (speedup 1.0000x reference)
#include <cuda_runtime.h>
#include <cstdint>

// ---------------------------------------------------------------------------
// BatchTopK: global top-k (k=98304) over 25,165,824 fp32, scatter relu'd
// values into zeros, EMA threshold update from min of top-k.
//
// Strategy: sampled guess threshold -> single full read+write pass that zeros
// the output and collects a small (~400k) candidate set -> exact 3-stage radix
// select on candidates -> scattered winner writes + exact tie handling.
// ---------------------------------------------------------------------------

#define K_TOTAL     98304u        // K * batch * layers = 32*512*6
#define EMA_E       0.003f
#define CANDCAP     2097152u      // candidate buffer capacity
#define EQCAP       4096u
#define SAMPLE_STRIDE 96
#define SAMPLE_TARGET 4096u       // sampled suffix count for guess bin
#define CHUNK_F4    2048          // float4s per block in main pass (8192 floats)
#define SCAP        1024u         // smem candidate staging per block

static __device__ unsigned g_hist_s[4096];
static __device__ unsigned g_histA[4096];
static __device__ unsigned g_histB[4096];
static __device__ unsigned g_hist8[256];
static __device__ unsigned g_cand_key[CANDCAP];
static __device__ unsigned g_cand_idx[CANDCAP];
static __device__ unsigned g_eq_idx[EQCAP];

struct Scalars {
    unsigned cand_cnt;
    unsigned eq_cnt;
    unsigned guess_bin;
    unsigned b12;
    unsigned rank1;
    unsigned m12;
    unsigned rank2;
    unsigned cutoff_key;
    unsigned need;
    unsigned count_eq;
    unsigned ambig;
    float    relu_cut;
};
static __device__ Scalars g_s;

// Monotone key: larger float -> larger unsigned key.
__device__ __forceinline__ unsigned fkey(float f) {
    unsigned u = __float_as_uint(f);
    return (u & 0x80000000u) ? ~u : (u | 0x80000000u);
}
__device__ __forceinline__ float kval(unsigned k) {
    unsigned u = (k & 0x80000000u) ? (k & 0x7FFFFFFFu) : ~k;
    return __uint_as_float(u);
}

// ---------------------------------------------------------------------------
__global__ void k_init() {
    int t = blockIdx.x * blockDim.x + threadIdx.x;
    int stride = gridDim.x * blockDim.x;
    for (int i = t; i < 4096; i += stride) {
        g_hist_s[i] = 0;
        g_histA[i]  = 0;
        g_histB[i]  = 0;
        if (i < 256) g_hist8[i] = 0;
    }
    if (t == 0) {
        g_s.cand_cnt = 0;
        g_s.eq_cnt = 0;
    }
}

// Strided sampling histogram (top 12 bits of key).
__global__ void k_sample(const float* __restrict__ x, int n) {
    long long i = (long long)(blockIdx.x * blockDim.x + threadIdx.x) * SAMPLE_STRIDE;
    if (i < n) {
        unsigned key = fkey(x[i]);
        atomicAdd(&g_hist_s[key >> 20], 1u);
    }
}

// Suffix-scan a 4096-bin histogram; find max bin with suffix >= k.
// stage 0: g_hist_s, k = SAMPLE_TARGET -> guess_bin
// stage 1: g_histA,  k = K_TOTAL      -> b12, rank1
// stage 2: g_histB,  k = rank1        -> m12, rank2
__global__ void k_scan(int stage) {
    const unsigned* hist = (stage == 0) ? g_hist_s : ((stage == 1) ? g_histA : g_histB);
    unsigned k = (stage == 0) ? SAMPLE_TARGET : ((stage == 1) ? K_TOTAL : g_s.rank1);

    __shared__ unsigned suf[256];
    int t = threadIdx.x;   // 256 threads

    unsigned p = 0;
    #pragma unroll
    for (int i = 0; i < 16; i++) p += hist[t * 16 + i];
    suf[t] = p;
    __syncthreads();

    // Hillis-Steele inclusive suffix scan over 256 partials.
    for (int d = 1; d < 256; d <<= 1) {
        unsigned v = (t + d < 256) ? suf[t + d] : 0u;
        __syncthreads();
        suf[t] += v;
        __syncthreads();
    }

    if (suf[0] < k) {
        // Degenerate (should not happen for this input); pick lowest bin.
        if (t == 0) {
            if (stage == 0)      g_s.guess_bin = 0;
            else if (stage == 1) { g_s.b12 = 0; g_s.rank1 = 1; }
            else                 { g_s.m12 = 0; g_s.rank2 = 1; }
        }
        return;
    }

    bool mine = (suf[t] >= k) && (t == 255 || suf[t + 1] < k);
    if (mine) {
        unsigned running = (t == 255) ? 0u : suf[t + 1];
        int b = t * 16;
        unsigned rem = 1;
        for (int i = 15; i >= 0; i--) {
            int bin = t * 16 + i;
            unsigned h = hist[bin];
            if (running + h >= k) { b = bin; rem = k - running; break; }
            running += h;
        }
        if (stage == 0)      g_s.guess_bin = (unsigned)b;
        else if (stage == 1) { g_s.b12 = (unsigned)b; g_s.rank1 = rem; }
        else                 { g_s.m12 = (unsigned)b; g_s.rank2 = rem; }
    }
}

// Main full pass: zero output, collect candidates via SMEM staging.
__global__ void __launch_bounds__(256) k_main(const float* __restrict__ x,
                                              float* __restrict__ out, int n4) {
    __shared__ unsigned s_key[SCAP];
    __shared__ unsigned s_idx[SCAP];
    __shared__ unsigned s_cnt, s_base;
    if (threadIdx.x == 0) s_cnt = 0;
    __syncthreads();

    unsigned gk = g_s.guess_bin << 20;
    const float4* x4 = (const float4*)x;
    float4* o4 = (float4*)out;
    int base = blockIdx.x * CHUNK_F4;

    #pragma unroll
    for (int it = 0; it < 8; it++) {
        int i4 = base + it * 256 + threadIdx.x;
        if (i4 < n4) {
            float4 v = x4[i4];
            o4[i4] = make_float4(0.f, 0.f, 0.f, 0.f);
            unsigned i0 = (unsigned)i4 * 4u;
            float vals[4] = {v.x, v.y, v.z, v.w};
            #pragma unroll
            for (int c = 0; c < 4; c++) {
                unsigned key = fkey(vals[c]);
                if (key >= gk) {
                    unsigned p = atomicAdd(&s_cnt, 1u);
                    if (p < SCAP) {
                        s_key[p] = key;
                        s_idx[p] = i0 + (unsigned)c;
                    } else {
                        unsigned g = atomicAdd(&g_s.cand_cnt, 1u);
                        if (g < CANDCAP) { g_cand_key[g] = key; g_cand_idx[g] = i0 + (unsigned)c; }
                    }
                }
            }
        }
    }
    __syncthreads();
    unsigned nloc = min(s_cnt, SCAP);
    if (threadIdx.x == 0) s_base = atomicAdd(&g_s.cand_cnt, nloc);
    __syncthreads();
    for (unsigned i = threadIdx.x; i < nloc; i += 256) {
        unsigned g = s_base + i;
        if (g < CANDCAP) { g_cand_key[g] = s_key[i]; g_cand_idx[g] = s_idx[i]; }
    }
}

// Candidate histograms. stage 0: top-12 bits -> g_histA.
// stage 1: mid-12 bits of keys matching b12 -> g_histB.
__global__ void k_hist_cand(int stage) {
    __shared__ unsigned sh[4096];
    for (int i = threadIdx.x; i < 4096; i += blockDim.x) sh[i] = 0;
    __syncthreads();

    unsigned n = min(g_s.cand_cnt, CANDCAP);
    unsigned b12 = g_s.b12;
    unsigned stride = gridDim.x * blockDim.x;
    for (unsigned j = blockIdx.x * blockDim.x + threadIdx.x; j < n; j += stride) {
        unsigned key = g_cand_key[j];
        if (stage == 0) {
            atomicAdd(&sh[key >> 20], 1u);
        } else {
            if ((key >> 20) == b12) atomicAdd(&sh[(key >> 8) & 0xFFFu], 1u);
        }
    }
    __syncthreads();
    unsigned* gh = stage ? g_histB : g_histA;
    for (int i = threadIdx.x; i < 4096; i += blockDim.x) {
        unsigned c = sh[i];
        if (c) atomicAdd(&gh[i], c);
    }
}

// Low-8-bit histogram of candidates matching the 24-bit prefix.
__global__ void k_histC() {
    unsigned n = min(g_s.cand_cnt, CANDCAP);
    unsigned pref = (g_s.b12 << 12) | g_s.m12;
    unsigned stride = gridDim.x * blockDim.x;
    for (unsigned j = blockIdx.x * blockDim.x + threadIdx.x; j < n; j += stride) {
        unsigned key = g_cand_key[j];
        if ((key >> 8) == pref) atomicAdd(&g_hist8[key & 0xFFu], 1u);
    }
}

// Finalize: exact cutoff key, tie info, threshold output.
__global__ void k_final(const float* __restrict__ thr, float* __restrict__ out, int ntot) {
    __shared__ unsigned suf[256];
    int t = threadIdx.x;  // 256 threads
    suf[t] = g_hist8[t];
    __syncthreads();
    for (int d = 1; d < 256; d <<= 1) {
        unsigned v = (t + d < 256) ? suf[t + d] : 0u;
        __syncthreads();
        suf[t] += v;
        __syncthreads();
    }
    unsigned k = g_s.rank2;
    bool mine = (suf[t] >= k) && (t == 255 || suf[t + 1] < k);
    if (suf[0] < k) mine = (t == 0);  // degenerate guard
    if (mine) {
        unsigned below = (t == 255) ? 0u : suf[t + 1];
        unsigned need = (k > below) ? (k - below) : 1u;
        unsigned ceq = g_hist8[t];
        unsigned ck = (g_s.b12 << 20) | (g_s.m12 << 8) | (unsigned)t;
        float cf = kval(ck);
        float rc = fmaxf(cf, 0.f);
        g_s.cutoff_key = ck;
        g_s.need = need;
        g_s.count_eq = ceq;
        g_s.ambig = (need != ceq) ? 1u : 0u;
        g_s.relu_cut = rc;
        out[ntot] = (1.0f - EMA_E) * thr[0] + EMA_E * rc;
    }
}

// Scatter winners: key > cutoff always in; key == cutoff in iff unambiguous,
// else defer to eq-fixup.
__global__ void k_winners(float* __restrict__ out) {
    unsigned n = min(g_s.cand_cnt, CANDCAP);
    unsigned ck = g_s.cutoff_key;
    unsigned ambig = g_s.ambig;
    float rc = g_s.relu_cut;
    unsigned stride = gridDim.x * blockDim.x;
    for (unsigned j = blockIdx.x * blockDim.x + threadIdx.x; j < n; j += stride) {
        unsigned key = g_cand_key[j];
        if (key > ck) {
            out[g_cand_idx[j]] = fmaxf(kval(key), 0.f);
        } else if (key == ck) {
            if (!ambig) {
                out[g_cand_idx[j]] = rc;
            } else {
                unsigned p = atomicAdd(&g_s.eq_cnt, 1u);
                if (p < EQCAP) g_eq_idx[p] = g_cand_idx[j];
            }
        }
    }
}

// Tie fixup: pick `need` smallest flat indices among equal-valued elements
// (JAX top_k tie-break: lower index first).
__global__ void k_eqfix(float* __restrict__ out) {
    if (!g_s.ambig) return;
    unsigned ne = min(g_s.eq_cnt, EQCAP);
    unsigned need = g_s.need;
    float rc = g_s.relu_cut;
    __shared__ unsigned smin[256];
    __shared__ unsigned sbest;
    for (unsigned sel = 0; sel < need; sel++) {
        unsigned m = 0xFFFFFFFFu;
        for (unsigned j = threadIdx.x; j < ne; j += 256) m = min(m, g_eq_idx[j]);
        smin[threadIdx.x] = m;
        __syncthreads();
        for (int d = 128; d > 0; d >>= 1) {
            if (threadIdx.x < (unsigned)d)
                smin[threadIdx.x] = min(smin[threadIdx.x], smin[threadIdx.x + d]);
            __syncthreads();
        }
        if (threadIdx.x == 0) sbest = smin[0];
        __syncthreads();
        unsigned best = sbest;
        if (best == 0xFFFFFFFFu) break;
        for (unsigned j = threadIdx.x; j < ne; j += 256)
            if (g_eq_idx[j] == best) g_eq_idx[j] = 0xFFFFFFFFu;
        if (threadIdx.x == 0) out[best] = rc;
        __syncthreads();
    }
}

// ---------------------------------------------------------------------------
extern "C" void kernel_launch(void* const* d_in, const int* in_sizes, int n_in,
                              void* d_out, int out_size) {
    const float* x   = (const float*)d_in[0];
    const float* thr = (const float*)d_in[1];
    float* out = (float*)d_out;

    int n = in_sizes[0];
    int n4 = n / 4;
    int ntot = out_size - 1;  // threshold lives in the last output slot

    k_init<<<16, 256>>>();

    int ns = (n + SAMPLE_STRIDE - 1) / SAMPLE_STRIDE;
    k_sample<<<(ns + 255) / 256, 256>>>(x, n);
    k_scan<<<1, 256>>>(0);

    int nchunks = (n4 + CHUNK_F4 - 1) / CHUNK_F4;
    k_main<<<nchunks, 256>>>(x, out, n4);

    k_hist_cand<<<256, 256>>>(0);
    k_scan<<<1, 256>>>(1);
    k_hist_cand<<<256, 256>>>(1);
    k_scan<<<1, 256>>>(2);
    k_histC<<<64, 256>>>();
    k_final<<<1, 256>>>(thr, out, ntot);
    k_winners<<<128, 256>>>(out);
    k_eqfix<<<1, 256>>>(out);
}

// round 2
// speedup vs baseline: 1.5969x; 1.5969x over previous
#include <cuda_runtime.h>
#include <cstdint>

// ---------------------------------------------------------------------------
// BatchTopK: global top-k (k=98304) over 25,165,824 fp32, scatter relu'd
// values into zeros, EMA threshold update from min of top-k.
//
// 3 launches total:
//   k_sample : init + sampled histogram + guess threshold (grid-barrier fused)
//   k_main   : single full read+write pass, zeros output, collects candidates
//   k_select : exact 3-level radix select + scatter + ties + EMA (grid-barrier fused)
// ---------------------------------------------------------------------------

#define K_TOTAL       98304u       // 32 * 512 * 6
#define EMA_E         0.003f
#define CANDCAP       2097152u
#define EQCAP         4096u
#define SAMPLE_TARGET 1024u        // sampled suffix count for guess bin
#define NB_SAMPLE     96           // <= 148 SMs -> co-resident, grid-spin safe
#define NB_SEL        128          // <= 148 SMs -> co-resident, grid-spin safe
#define CHUNK_F4      2048
#define SCAP          1024u

static __device__ unsigned g_hist_s[4096];
static __device__ unsigned g_histA[4096];
static __device__ unsigned g_histB[4096];
static __device__ unsigned g_hist8[256];
static __device__ unsigned g_cand_key[CANDCAP];
static __device__ unsigned g_cand_idx[CANDCAP];
static __device__ unsigned g_eq_idx[EQCAP];
static __device__ unsigned g_cand_cnt;
static __device__ unsigned g_eq_cnt;
static __device__ unsigned g_guess_key;
static __device__ float    g_guess_f;
// Software grid barriers: accumulating counters + per-launch base (no reset race
// across CUDA-graph replays).
static __device__ unsigned g_bar_smp, g_base_smp;
static __device__ unsigned g_bar_sel, g_base_sel;

// Monotone key: larger float -> larger unsigned key.
__device__ __forceinline__ unsigned fkey(float f) {
    unsigned u = __float_as_uint(f);
    return (u & 0x80000000u) ? ~u : (u | 0x80000000u);
}
__device__ __forceinline__ float kval(unsigned k) {
    unsigned u = (k & 0x80000000u) ? (k & 0x7FFFFFFFu) : ~k;
    return __uint_as_float(u);
}

// Grid barrier: all blocks co-resident (grid <= #SMs). Producer fence before
// arrive; consumers spin on the counter then fence.
__device__ __forceinline__ void grid_bar(unsigned* bar, unsigned target) {
    __syncthreads();
    if (threadIdx.x == 0) {
        __threadfence();
        atomicAdd(bar, 1u);
        while (atomicAdd(bar, 0u) < target) __nanosleep(64);
    }
    __syncthreads();
    __threadfence();
}

// Warp-aggregated shared-memory histogram add (reduces ATOMS conflict cost).
__device__ __forceinline__ void wagg_add(unsigned* sh, unsigned bin, bool valid) {
    unsigned lane = threadIdx.x & 31u;
    unsigned b = valid ? bin : (0x10000u + lane);   // distinct fake bins
    unsigned m = __match_any_sync(0xFFFFFFFFu, b);
    if (valid && (unsigned)(__ffs(m) - 1) == lane)
        atomicAdd(&sh[bin], (unsigned)__popc(m));
}

// Block-wide: suffix-scan histogram of 256*PER bins, find max bin with
// suffix >= k, plus remaining rank within that bin. Results in *s_bin,*s_rem.
template <int PER>
__device__ void suffix_pick(const unsigned* hist, unsigned k,
                            unsigned* s_scan, unsigned* s_bin, unsigned* s_rem) {
    int t = threadIdx.x;   // 256 threads
    unsigned p = 0;
    #pragma unroll
    for (int i = 0; i < PER; i++) p += hist[t * PER + i];
    s_scan[t] = p;
    __syncthreads();
    for (int d = 1; d < 256; d <<= 1) {
        unsigned v = (t + d < 256) ? s_scan[t + d] : 0u;
        __syncthreads();
        s_scan[t] += v;
        __syncthreads();
    }
    if (s_scan[0] < k) {
        if (t == 0) { *s_bin = 0; *s_rem = 1; }   // degenerate guard
    } else {
        bool mine = (s_scan[t] >= k) && (t == 255 || s_scan[t + 1] < k);
        if (mine) {
            unsigned running = (t == 255) ? 0u : s_scan[t + 1];
            unsigned bsel = (unsigned)(t * PER);
            unsigned rem = 1;
            for (int i = PER - 1; i >= 0; i--) {
                unsigned h = hist[t * PER + i];
                if (running + h >= k) { bsel = (unsigned)(t * PER + i); rem = k - running; break; }
                running += h;
            }
            *s_bin = bsel; *s_rem = rem;
        }
    }
    __syncthreads();
}

// ---------------------------------------------------------------------------
// Kernel 1: init all global state + sampled histogram + guess-bin selection.
__global__ void __launch_bounds__(256) k_sample(const float* __restrict__ x, int n) {
    __shared__ unsigned sh[4096];
    __shared__ unsigned s_scan[256];
    __shared__ unsigned s_bin, s_rem;
    int t = threadIdx.x;
    int gid = blockIdx.x * 256 + t;
    const int nthr = NB_SAMPLE * 256;
    unsigned base = g_base_smp;

    // zero all global state (sliced across grid)
    for (int i = gid; i < 4096; i += nthr) { g_hist_s[i] = 0; g_histA[i] = 0; g_histB[i] = 0; }
    if (gid < 256) g_hist8[gid] = 0;
    if (gid == 0) { g_cand_cnt = 0; g_eq_cnt = 0; }

    for (int i = t; i < 4096; i += 256) sh[i] = 0;
    __syncthreads();

    // sample every 256th element
    int nsamp = n >> 8;
    int per = (nsamp + nthr - 1) / nthr;
    for (int s = 0; s < per; s++) {
        int j = gid + s * nthr;
        bool valid = j < nsamp;
        unsigned bin = 0;
        if (valid) bin = fkey(x[(long long)j << 8]) >> 20;
        wagg_add(sh, bin, valid);
    }
    __syncthreads();
    grid_bar(&g_bar_smp, base + NB_SAMPLE);         // global zeroing done
    for (int i = t; i < 4096; i += 256) {
        unsigned c = sh[i];
        if (c) atomicAdd(&g_hist_s[i], c);
    }
    grid_bar(&g_bar_smp, base + 2 * NB_SAMPLE);     // merges done
    if (blockIdx.x == 0) {
        suffix_pick<16>(g_hist_s, SAMPLE_TARGET, s_scan, &s_bin, &s_rem);
        if (t == 0) {
            unsigned gb = s_bin;
            g_guess_key = gb << 20;
            g_guess_f = kval(gb << 20);
            g_base_smp = base + 2 * NB_SAMPLE;      // barrier base for next replay
        }
    }
}

// ---------------------------------------------------------------------------
// Kernel 2: the only full pass. Zero output, collect candidates >= guess.
__global__ void __launch_bounds__(256) k_main(const float4* __restrict__ x4,
                                              float4* __restrict__ o4, int n4) {
    __shared__ unsigned s_key[SCAP];
    __shared__ unsigned s_idx[SCAP];
    __shared__ unsigned s_cnt, s_base;
    if (threadIdx.x == 0) s_cnt = 0;
    __syncthreads();

    float gf = g_guess_f;
    int base = blockIdx.x * CHUNK_F4 + threadIdx.x;
    float4 v[8];
    const float4 z4 = make_float4(0.f, 0.f, 0.f, 0.f);

    if ((blockIdx.x + 1) * CHUNK_F4 <= n4) {
        #pragma unroll
        for (int it = 0; it < 8; it++) v[it] = x4[base + it * 256];
        #pragma unroll
        for (int it = 0; it < 8; it++) o4[base + it * 256] = z4;
    } else {
        #pragma unroll
        for (int it = 0; it < 8; it++) {
            int i = base + it * 256;
            if (i < n4) { v[it] = x4[i]; o4[i] = z4; }
            else v[it] = make_float4(-1e30f, -1e30f, -1e30f, -1e30f);
        }
    }

    #pragma unroll
    for (int it = 0; it < 8; it++) {
        int i4 = base + it * 256;
        float vv[4] = {v[it].x, v[it].y, v[it].z, v[it].w};
        #pragma unroll
        for (int c = 0; c < 4; c++) {
            if (vv[c] >= gf) {                       // float cmp: skip fkey off-path
                unsigned p = atomicAdd(&s_cnt, 1u);
                unsigned key = fkey(vv[c]);
                unsigned idx = ((unsigned)i4 << 2) + (unsigned)c;
                if (p < SCAP) { s_key[p] = key; s_idx[p] = idx; }
                else {
                    unsigned g = atomicAdd(&g_cand_cnt, 1u);
                    if (g < CANDCAP) { g_cand_key[g] = key; g_cand_idx[g] = idx; }
                }
            }
        }
    }
    __syncthreads();
    unsigned nloc = min(s_cnt, SCAP);
    if (threadIdx.x == 0) s_base = atomicAdd(&g_cand_cnt, nloc);
    __syncthreads();
    for (unsigned i = threadIdx.x; i < nloc; i += 256) {
        unsigned g = s_base + i;
        if (g < CANDCAP) { g_cand_key[g] = s_key[i]; g_cand_idx[g] = s_idx[i]; }
    }
}

// ---------------------------------------------------------------------------
// Kernel 3: exact select over candidates + scatter + ties + threshold EMA.
__global__ void __launch_bounds__(256) k_select(const float* __restrict__ thr,
                                                float* __restrict__ out, int ntot) {
    __shared__ unsigned sh[4096];
    __shared__ unsigned s_scan[256];
    __shared__ unsigned s_bin, s_rem;
    int t = threadIdx.x;
    unsigned bbase = g_base_sel;
    unsigned n = min(g_cand_cnt, CANDCAP);
    const unsigned nthr = NB_SEL * 256;
    unsigned iters = (n + nthr - 1) / nthr;
    unsigned gidx = blockIdx.x * 256 + t;

    // ---- Phase A: top-12-bit histogram of all candidates ----
    for (int i = t; i < 4096; i += 256) sh[i] = 0;
    __syncthreads();
    for (unsigned s = 0; s < iters; s++) {
        unsigned j = gidx + s * nthr;
        bool valid = j < n;
        unsigned bin = valid ? (g_cand_key[j] >> 20) : 0u;
        wagg_add(sh, bin, valid);
    }
    __syncthreads();
    for (int i = t; i < 4096; i += 256) {
        unsigned c = sh[i];
        if (c) atomicAdd(&g_histA[i], c);
    }
    grid_bar(&g_bar_sel, bbase + NB_SEL);
    suffix_pick<16>(g_histA, K_TOTAL, s_scan, &s_bin, &s_rem);
    unsigned b12 = s_bin, rank1 = s_rem;
    __syncthreads();

    // ---- Phase B: mid-12-bit histogram of candidates in bin b12 ----
    for (int i = t; i < 4096; i += 256) sh[i] = 0;
    __syncthreads();
    for (unsigned s = 0; s < iters; s++) {
        unsigned j = gidx + s * nthr;
        bool valid = j < n;
        unsigned key = valid ? g_cand_key[j] : 0u;
        valid = valid && ((key >> 20) == b12);
        wagg_add(sh, (key >> 8) & 0xFFFu, valid);
    }
    __syncthreads();
    for (int i = t; i < 4096; i += 256) {
        unsigned c = sh[i];
        if (c) atomicAdd(&g_histB[i], c);
    }
    grid_bar(&g_bar_sel, bbase + 2 * NB_SEL);
    suffix_pick<16>(g_histB, rank1, s_scan, &s_bin, &s_rem);
    unsigned m12 = s_bin, rank2 = s_rem;
    unsigned pref = (b12 << 12) | m12;
    __syncthreads();

    // ---- Phase C: low-8-bit histogram of candidates matching 24-bit prefix ----
    if (t < 256) sh[t] = 0;
    __syncthreads();
    for (unsigned s = 0; s < iters; s++) {
        unsigned j = gidx + s * nthr;
        bool valid = j < n;
        unsigned key = valid ? g_cand_key[j] : 0u;
        valid = valid && ((key >> 8) == pref);
        wagg_add(sh, key & 0xFFu, valid);
    }
    __syncthreads();
    {
        unsigned c = sh[t];
        if (c) atomicAdd(&g_hist8[t], c);
    }
    grid_bar(&g_bar_sel, bbase + 3 * NB_SEL);
    suffix_pick<1>(g_hist8, rank2, s_scan, &s_bin, &s_rem);
    unsigned lo8 = s_bin, need = s_rem;
    unsigned count_eq = g_hist8[lo8];
    unsigned ck = (pref << 8) | lo8;                 // exact cutoff key
    bool ambig = (need != count_eq);
    float rc = fmaxf(kval(ck), 0.f);

    // ---- Phase D: winner scatter ----
    for (unsigned s = 0; s < iters; s++) {
        unsigned j = gidx + s * nthr;
        if (j < n) {
            unsigned key = g_cand_key[j];
            if (key > ck) {
                out[g_cand_idx[j]] = fmaxf(kval(key), 0.f);
            } else if (key == ck) {
                if (!ambig) out[g_cand_idx[j]] = rc;
                else {
                    unsigned p = atomicAdd(&g_eq_cnt, 1u);
                    if (p < EQCAP) g_eq_idx[p] = g_cand_idx[j];
                }
            }
        }
    }
    if (blockIdx.x == 0 && t == 0)
        out[ntot] = (1.0f - EMA_E) * thr[0] + EMA_E * rc;

    grid_bar(&g_bar_sel, bbase + 4 * NB_SEL);

    // ---- Phase E: tie fixup (JAX tie-break: lowest flat index wins) ----
    if (blockIdx.x == 0) {
        if (t == 0) g_base_sel = bbase + 4 * NB_SEL;  // barrier base for next replay
        if (ambig) {
            unsigned ne = min(g_eq_cnt, EQCAP);
            __shared__ unsigned smin[256];
            __shared__ unsigned sbest;
            for (unsigned sel = 0; sel < need; sel++) {
                unsigned m = 0xFFFFFFFFu;
                for (unsigned j = t; j < ne; j += 256) m = min(m, g_eq_idx[j]);
                smin[t] = m;
                __syncthreads();
                for (int d = 128; d > 0; d >>= 1) {
                    if (t < d) smin[t] = min(smin[t], smin[t + d]);
                    __syncthreads();
                }
                if (t == 0) sbest = smin[0];
                __syncthreads();
                unsigned best = sbest;
                if (best == 0xFFFFFFFFu) break;
                for (unsigned j = t; j < ne; j += 256)
                    if (g_eq_idx[j] == best) g_eq_idx[j] = 0xFFFFFFFFu;
                if (t == 0) out[best] = rc;
                __syncthreads();
            }
        }
    }
}

// ---------------------------------------------------------------------------
extern "C" void kernel_launch(void* const* d_in, const int* in_sizes, int n_in,
                              void* d_out, int out_size) {
    const float* x   = (const float*)d_in[0];
    const float* thr = (const float*)d_in[1];
    float* out = (float*)d_out;

    int n = in_sizes[0];
    int n4 = n / 4;
    int ntot = out_size - 1;   // threshold lives in the last output slot

    k_sample<<<NB_SAMPLE, 256>>>(x, n);

    int nchunks = (n4 + CHUNK_F4 - 1) / CHUNK_F4;
    k_main<<<nchunks, 256>>>((const float4*)x, (float4*)out, n4);

    k_select<<<NB_SEL, 256>>>(thr, out, ntot);
}

// round 3
// speedup vs baseline: 1.6668x; 1.0438x over previous
#include <cuda_runtime.h>
#include <cstdint>

// ---------------------------------------------------------------------------
// BatchTopK fully fused: ONE persistent kernel.
//   phase 0: sampled 12-bit histogram -> guess threshold
//   phase 1: full read+write pass (zeros output, collects candidates),
//            dynamic chunk stealing
//   phase 2-4: exact 3-level radix select on candidates
//   phase 5: winner scatter + EMA threshold + tie fixup
// Global state is re-zeroed at end-of-kernel for the next graph replay.
// ---------------------------------------------------------------------------

#define K_TOTAL       98304u       // 32 * 512 * 6
#define EMA_E         0.003f
#define CANDCAP       2097152u
#define EQCAP         4096u
#define SAMPLE_TARGET 1024u
#define NB            444          // 148 SMs * 3 -> co-resident guaranteed
#define NT            256
#define NTHR          (NB * NT)
#define SCAP          2048u
#define CHUNK_F4      2048         // 256 threads * 8 float4

static __device__ unsigned g_hist_s[4096];
static __device__ unsigned g_histA[4096];
static __device__ unsigned g_histB[4096];
static __device__ unsigned g_hist8[256];
static __device__ unsigned g_cand_key[CANDCAP];
static __device__ unsigned g_cand_idx[CANDCAP];
static __device__ unsigned g_eq_idx[EQCAP];
static __device__ unsigned g_cand_cnt;
static __device__ unsigned g_eq_cnt;
static __device__ unsigned g_chunk;
static __device__ unsigned g_bar;     // accumulating barrier counter
static __device__ unsigned g_base;    // barrier base (advances every run)

__device__ __forceinline__ unsigned fkey(float f) {
    unsigned u = __float_as_uint(f);
    return (u & 0x80000000u) ? ~u : (u | 0x80000000u);
}
__device__ __forceinline__ float kval(unsigned k) {
    unsigned u = (k & 0x80000000u) ? (k & 0x7FFFFFFFu) : ~k;
    return __uint_as_float(u);
}

__device__ __forceinline__ void grid_bar(unsigned target) {
    __syncthreads();
    if (threadIdx.x == 0) {
        __threadfence();
        atomicAdd(&g_bar, 1u);
        int backoff = 32;
        while (atomicAdd(&g_bar, 0u) < target) {
            __nanosleep(backoff);
            if (backoff < 256) backoff <<= 1;
        }
    }
    __syncthreads();
    __threadfence();
}

// Warp-aggregated shared-memory histogram add.
__device__ __forceinline__ void wagg_add(unsigned* sh, unsigned bin, bool valid) {
    unsigned lane = threadIdx.x & 31u;
    unsigned b = valid ? bin : (0x10000u + lane);
    unsigned m = __match_any_sync(0xFFFFFFFFu, b);
    if (valid && (unsigned)(__ffs(m) - 1) == lane)
        atomicAdd(&sh[bin], (unsigned)__popc(m));
}

// Block-redundant: suffix-scan 256*PER-bin histogram; max bin with suffix >= k.
template <int PER>
__device__ void suffix_pick(const unsigned* hist, unsigned k,
                            unsigned* s_scan, unsigned* s_bin, unsigned* s_rem) {
    int t = threadIdx.x;
    unsigned p = 0;
    #pragma unroll
    for (int i = 0; i < PER; i++) p += hist[t * PER + i];
    s_scan[t] = p;
    __syncthreads();
    for (int d = 1; d < 256; d <<= 1) {
        unsigned v = (t + d < 256) ? s_scan[t + d] : 0u;
        __syncthreads();
        s_scan[t] += v;
        __syncthreads();
    }
    if (s_scan[0] < k) {
        if (t == 0) { *s_bin = 0; *s_rem = 1; }
    } else {
        bool mine = (s_scan[t] >= k) && (t == 255 || s_scan[t + 1] < k);
        if (mine) {
            unsigned running = (t == 255) ? 0u : s_scan[t + 1];
            unsigned bsel = (unsigned)(t * PER);
            unsigned rem = 1;
            for (int i = PER - 1; i >= 0; i--) {
                unsigned h = hist[t * PER + i];
                if (running + h >= k) { bsel = (unsigned)(t * PER + i); rem = k - running; break; }
                running += h;
            }
            *s_bin = bsel; *s_rem = rem;
        }
    }
    __syncthreads();
}

// ---------------------------------------------------------------------------
__global__ void __launch_bounds__(NT, 3)
k_all(const float* __restrict__ x, const float4* __restrict__ x4,
      float4* __restrict__ o4, const float* __restrict__ thr,
      float* __restrict__ out, int n, int n4, int ntot) {
    __shared__ union {
        unsigned hist[4096];
        struct { unsigned key[SCAP]; unsigned idx[SCAP]; } st;
    } u;
    __shared__ unsigned s_scan[256];
    __shared__ unsigned s_bin, s_rem, s_cnt, s_gbase, s_chunk;

    const int t = threadIdx.x;
    const unsigned gid = blockIdx.x * NT + t;
    const unsigned base = g_base;

    // ---------------- Phase 0: sampled histogram -> guess ----------------
    for (int i = t; i < 4096; i += NT) u.hist[i] = 0;
    __syncthreads();
    int nsamp = n >> 8;                        // sample every 256th element
    int sit = (nsamp + NTHR - 1) / NTHR;
    for (int s = 0; s < sit; s++) {
        int j = (int)gid + s * NTHR;
        bool v = j < nsamp;
        unsigned bin = v ? (fkey(x[(size_t)j << 8]) >> 20) : 0u;
        wagg_add(u.hist, bin, v);
    }
    __syncthreads();
    for (int i = t; i < 4096; i += NT) {
        unsigned c = u.hist[i];
        if (c) atomicAdd(&g_hist_s[i], c);
    }
    grid_bar(base + NB);                                         // bar1
    suffix_pick<16>(g_hist_s, SAMPLE_TARGET, s_scan, &s_bin, &s_rem);
    const float gf = kval(s_bin << 20);

    // ---------------- Phase 1: full pass (dynamic chunk stealing) --------
    if (t == 0) s_cnt = 0;
    __syncthreads();
    const int nchunks = (n4 + CHUNK_F4 - 1) / CHUNK_F4;
    const float4 z4 = make_float4(0.f, 0.f, 0.f, 0.f);
    for (;;) {
        if (t == 0) s_chunk = atomicAdd(&g_chunk, 1u);
        __syncthreads();
        unsigned ch = s_chunk;
        if (ch >= (unsigned)nchunks) break;
        int bbase = (int)ch * CHUNK_F4 + t;
        float4 v[8];
        if ((int)(ch + 1) * CHUNK_F4 <= n4) {
            #pragma unroll
            for (int i = 0; i < 8; i++) v[i] = __ldcs(&x4[bbase + i * NT]);
            #pragma unroll
            for (int i = 0; i < 8; i++) __stcs(&o4[bbase + i * NT], z4);
        } else {
            #pragma unroll
            for (int i = 0; i < 8; i++) {
                int idx = bbase + i * NT;
                if (idx < n4) { v[i] = __ldcs(&x4[idx]); __stcs(&o4[idx], z4); }
                else v[i] = make_float4(-1e30f, -1e30f, -1e30f, -1e30f);
            }
        }
        #pragma unroll
        for (int i = 0; i < 8; i++) {
            int i4 = bbase + i * NT;
            float vv[4] = {v[i].x, v[i].y, v[i].z, v[i].w};
            #pragma unroll
            for (int c = 0; c < 4; c++) {
                if (vv[c] >= gf) {
                    unsigned p = atomicAdd(&s_cnt, 1u);
                    unsigned key = fkey(vv[c]);
                    unsigned idx = ((unsigned)i4 << 2) + (unsigned)c;
                    if (p < SCAP) { u.st.key[p] = key; u.st.idx[p] = idx; }
                    else {
                        unsigned g = atomicAdd(&g_cand_cnt, 1u);
                        if (g < CANDCAP) { g_cand_key[g] = key; g_cand_idx[g] = idx; }
                    }
                }
            }
        }
        __syncthreads();
        unsigned nloc = min(s_cnt, SCAP);
        if (nloc) {
            if (t == 0) s_gbase = atomicAdd(&g_cand_cnt, nloc);
            __syncthreads();
            for (unsigned i = t; i < nloc; i += NT) {
                unsigned g = s_gbase + i;
                if (g < CANDCAP) { g_cand_key[g] = u.st.key[i]; g_cand_idx[g] = u.st.idx[i]; }
            }
        }
        __syncthreads();
        if (t == 0) s_cnt = 0;
        __syncthreads();
    }
    grid_bar(base + 2 * NB);                                     // bar2

    const unsigned ncand = min(g_cand_cnt, CANDCAP);
    const unsigned cit = (ncand + NTHR - 1) / NTHR;

    // ---------------- Phase 2: top-12-bit histogram ----------------------
    for (int i = t; i < 4096; i += NT) u.hist[i] = 0;
    __syncthreads();
    for (unsigned s = 0; s < cit; s++) {
        unsigned j = gid + s * NTHR;
        bool v = j < ncand;
        unsigned bin = v ? (g_cand_key[j] >> 20) : 0u;
        wagg_add(u.hist, bin, v);
    }
    __syncthreads();
    for (int i = t; i < 4096; i += NT) {
        unsigned c = u.hist[i];
        if (c) atomicAdd(&g_histA[i], c);
    }
    for (unsigned i = gid; i < 4096; i += NTHR) g_hist_s[i] = 0;   // re-zero for next run
    grid_bar(base + 3 * NB);                                     // bar3
    suffix_pick<16>(g_histA, K_TOTAL, s_scan, &s_bin, &s_rem);
    const unsigned b12 = s_bin, rank1 = s_rem;

    // ---------------- Phase 3: mid-12-bit histogram ----------------------
    for (int i = t; i < 4096; i += NT) u.hist[i] = 0;
    __syncthreads();
    for (unsigned s = 0; s < cit; s++) {
        unsigned j = gid + s * NTHR;
        bool v = j < ncand;
        unsigned key = v ? g_cand_key[j] : 0u;
        v = v && ((key >> 20) == b12);
        wagg_add(u.hist, (key >> 8) & 0xFFFu, v);
    }
    __syncthreads();
    for (int i = t; i < 4096; i += NT) {
        unsigned c = u.hist[i];
        if (c) atomicAdd(&g_histB[i], c);
    }
    grid_bar(base + 4 * NB);                                     // bar4
    suffix_pick<16>(g_histB, rank1, s_scan, &s_bin, &s_rem);
    const unsigned m12 = s_bin, rank2 = s_rem;
    const unsigned pref = (b12 << 12) | m12;

    // ---------------- Phase 4: low-8-bit histogram -----------------------
    if (t < 256) u.hist[t] = 0;
    __syncthreads();
    for (unsigned s = 0; s < cit; s++) {
        unsigned j = gid + s * NTHR;
        bool v = j < ncand;
        unsigned key = v ? g_cand_key[j] : 0u;
        v = v && ((key >> 8) == pref);
        wagg_add(u.hist, key & 0xFFu, v);
    }
    __syncthreads();
    {
        unsigned c = u.hist[t];
        if (c) atomicAdd(&g_hist8[t], c);
    }
    for (unsigned i = gid; i < 4096; i += NTHR) g_histA[i] = 0;    // re-zero
    grid_bar(base + 5 * NB);                                     // bar5
    suffix_pick<1>(g_hist8, rank2, s_scan, &s_bin, &s_rem);
    const unsigned lo8 = s_bin, need = s_rem;
    const unsigned count_eq = g_hist8[lo8];
    const unsigned ck = (pref << 8) | lo8;
    const bool ambig = (need != count_eq);
    const float rc = fmaxf(kval(ck), 0.f);

    // ---------------- Phase 5: winner scatter + EMA ----------------------
    for (unsigned s = 0; s < cit; s++) {
        unsigned j = gid + s * NTHR;
        if (j < ncand) {
            unsigned key = g_cand_key[j];
            if (key > ck) {
                out[g_cand_idx[j]] = fmaxf(kval(key), 0.f);
            } else if (key == ck) {
                if (!ambig) out[g_cand_idx[j]] = rc;
                else {
                    unsigned p = atomicAdd(&g_eq_cnt, 1u);
                    if (p < EQCAP) g_eq_idx[p] = g_cand_idx[j];
                }
            }
        }
    }
    if (gid == 0) out[ntot] = (1.0f - EMA_E) * thr[0] + EMA_E * rc;
    for (unsigned i = gid; i < 4096; i += NTHR) g_histB[i] = 0;    // re-zero
    grid_bar(base + 6 * NB);                                     // bar6

    // ---------------- Tail: re-zero state, tie fixup ---------------------
    if (gid < 256) g_hist8[gid] = 0;
    if (gid == 0) { g_cand_cnt = 0; g_chunk = 0; }

    if (blockIdx.x == 0) {
        if (t == 0) g_base = base + 6 * NB;
        if (ambig) {
            // JAX tie-break: lowest flat index wins among equal-valued elems.
            unsigned ne = min(g_eq_cnt, EQCAP);
            __shared__ unsigned smin[256];
            __shared__ unsigned sbest;
            for (unsigned sel = 0; sel < need; sel++) {
                unsigned m = 0xFFFFFFFFu;
                for (unsigned j = t; j < ne; j += NT) m = min(m, g_eq_idx[j]);
                smin[t] = m;
                __syncthreads();
                for (int d = 128; d > 0; d >>= 1) {
                    if (t < d) smin[t] = min(smin[t], smin[t + d]);
                    __syncthreads();
                }
                if (t == 0) sbest = smin[0];
                __syncthreads();
                unsigned best = sbest;
                if (best == 0xFFFFFFFFu) break;
                for (unsigned j = t; j < ne; j += NT)
                    if (g_eq_idx[j] == best) g_eq_idx[j] = 0xFFFFFFFFu;
                if (t == 0) out[best] = rc;
                __syncthreads();
            }
        }
        if (t == 0) g_eq_cnt = 0;
    }
}

// ---------------------------------------------------------------------------
extern "C" void kernel_launch(void* const* d_in, const int* in_sizes, int n_in,
                              void* d_out, int out_size) {
    const float* x   = (const float*)d_in[0];
    const float* thr = (const float*)d_in[1];
    float* out = (float*)d_out;

    int n = in_sizes[0];
    int n4 = n / 4;
    int ntot = out_size - 1;   // threshold in last output slot

    k_all<<<NB, NT>>>(x, (const float4*)x, (float4*)out, thr, out, n, n4, ntot);
}